// round 10
// baseline (speedup 1.0000x reference)
#include <cuda_runtime.h>
#include <cuda_fp16.h>
#include <cstdint>

// Problem dims
#define TOKENS 8192
#define IN_F   4096
#define OUT_F  4096
#define GROUPS (OUT_F * IN_F / 64)   // 262144
#define HALF_G (GROUPS / 2)          // 131072
#define PACKED (HALF_G * 64)         // 8388608

// Scratch: fp16 copies of x and dequantized W (device globals — no allocs)
__device__ __align__(1024) __half g_X16[(size_t)TOKENS * IN_F];  // 64 MB
__device__ __align__(1024) __half g_W16[(size_t)OUT_F * IN_F];   // 32 MB

// ============================================================================
// Merged prep kernel: half the blocks convert x fp32->fp16, half dequant W.
// Both halves are DRAM-streaming; merging overlaps their memory traffic.
// ============================================================================
#define PREP_BLOCKS 8192
#define PREP_SPLIT  4096

__global__ void prep_kernel(const float4* __restrict__ x, uint2* __restrict__ oX,
                            const int* __restrict__ Wq, const float* __restrict__ scale,
                            const float* __restrict__ zero, __half* __restrict__ w16) {
    if (blockIdx.x < PREP_SPLIT) {
        const int n4 = TOKENS * IN_F / 4;
        for (int i = blockIdx.x * blockDim.x + threadIdx.x; i < n4;
             i += PREP_SPLIT * blockDim.x) {
            float4 v = x[i];
            union { __half2 h; unsigned u; } c0, c1;
            c0.h = __floats2half2_rn(v.x, v.y);
            c1.h = __floats2half2_rn(v.z, v.w);
            uint2 u; u.x = c0.u; u.y = c1.u;
            oX[i] = u;
        }
    } else {
        for (int i = (blockIdx.x - PREP_SPLIT) * blockDim.x + threadIdx.x; i < PACKED;
             i += (PREP_BLOCKS - PREP_SPLIT) * blockDim.x) {
            int q = Wq[i];
            int g = i >> 6;
            float s1 = __ldg(scale + g),          z1 = __ldg(zero + g);
            float s2 = __ldg(scale + g + HALF_G), z2 = __ldg(zero + g + HALF_G);
            w16[i]          = __float2half_rn(((float)((q >> 4) & 0xF) - z1) * s1);
            w16[i + PACKED] = __float2half_rn(((float)(q & 0xF)        - z2) * s2);
        }
    }
}

// ============================================================================
// GEMM: out[8192,4096] = X16 @ W16^T + bias
// fp16 inputs, fp16 mma accumulation over K=32 windows, promoted to fp32.
// CTA tile 128(M) x 128(N) x 64(K), 3 cp.async stages, 256 threads.
// Warp grid 2(m) x 4(n): each warp owns 64x32 (4 m16 x 4 n8 frags).
// SMEM rows padded to 72 halves (144B): row stride = 36 banks = 4 (mod 32),
// each 8-row ldmatrix phase hits 8 disjoint 4-bank spans -> conflict-free.
// ============================================================================
#define BM 128
#define BN 128
#define BK 64
#define STAGES 3
#define ROW_HALFS 72
#define ROW_BYTES (ROW_HALFS * 2)              // 144
#define A_TILE_BYTES (BM * ROW_BYTES)          // 18432
#define B_TILE_BYTES (BN * ROW_BYTES)          // 18432
#define STAGE_BYTES (A_TILE_BYTES + B_TILE_BYTES)   // 36864
#define SMEM_TOTAL (STAGES * STAGE_BYTES)      // 110592

__device__ __forceinline__ uint32_t smem_u32(const void* p) {
    uint32_t a;
    asm("{ .reg .u64 t; cvta.to.shared.u64 t, %1; cvt.u32.u64 %0, t; }"
        : "=r"(a) : "l"(p));
    return a;
}

#define CP_ASYNC_16(dst_u32, src_ptr) \
    asm volatile("cp.async.cg.shared.global [%0], [%1], 16;" \
        :: "r"(dst_u32), "l"(src_ptr) : "memory")
#define CP_COMMIT() asm volatile("cp.async.commit_group;" ::: "memory")
#define CP_WAIT(n)  asm volatile("cp.async.wait_group %0;" :: "n"(n) : "memory")

#define LDSM_X4(r0, r1, r2, r3, addr) \
    asm volatile("ldmatrix.sync.aligned.m8n8.x4.shared.b16 {%0,%1,%2,%3}, [%4];" \
        : "=r"(r0), "=r"(r1), "=r"(r2), "=r"(r3) : "r"(addr))

// fp16-accumulate variant: D/C are 2 x .f16x2 regs
#define MMA_16816_F16(d0, d1, a0, a1, a2, a3, b0, b1) \
    asm volatile("mma.sync.aligned.m16n8k16.row.col.f16.f16.f16.f16 " \
        "{%0,%1}, {%2,%3,%4,%5}, {%6,%7}, {%0,%1};" \
        : "+r"(d0), "+r"(d1) \
        : "r"(a0), "r"(a1), "r"(a2), "r"(a3), "r"(b0), "r"(b1))

__global__ void __launch_bounds__(256, 2)
gemm_f16_kernel(const __half* __restrict__ X16, const __half* __restrict__ W16,
                const float* __restrict__ bias, float* __restrict__ out) {
    extern __shared__ __align__(128) char smem[];
    const uint32_t sb = smem_u32(smem);
    const int tid = threadIdx.x;
    const int wid = tid >> 5, lid = tid & 31;
    const int warp_m = wid & 1;        // 0..1 -> 64 rows
    const int warp_n = wid >> 1;       // 0..3 -> 32 cols
    const int bn = blockIdx.x, bm = blockIdx.y;

    // ---- cp.async slots: each tile [128][64] = 1024 16B vectors, 4/thread ----
    const __half* gAbase = X16 + (size_t)(bm * BM) * IN_F;
    const __half* gBbase = W16 + (size_t)(bn * BN) * IN_F;
    uint32_t sOff[4];
    const __half* gA[4];
    const __half* gB[4];
    #pragma unroll
    for (int i = 0; i < 4; i++) {
        int v = tid + 256 * i;
        int r = v >> 3, c8 = v & 7;
        sOff[i] = r * ROW_BYTES + c8 * 16;
        gA[i] = gAbase + (size_t)r * IN_F + c8 * 8;
        gB[i] = gBbase + (size_t)r * IN_F + c8 * 8;
    }

    float c[4][4][4];
    #pragma unroll
    for (int mi = 0; mi < 4; mi++)
        #pragma unroll
        for (int nf = 0; nf < 4; nf++)
            c[mi][nf][0] = c[mi][nf][1] = c[mi][nf][2] = c[mi][nf][3] = 0.f;

    uint32_t ch[4][4][2];   // fp16 window accumulators (half2 pairs)
    #pragma unroll
    for (int mi = 0; mi < 4; mi++)
        #pragma unroll
        for (int nf = 0; nf < 4; nf++)
            ch[mi][nf][0] = ch[mi][nf][1] = 0u;

    const int NK = IN_F / BK;  // 64

    // ---- prologue ----
    #pragma unroll
    for (int s = 0; s < STAGES - 1; s++) {
        uint32_t st = sb + s * STAGE_BYTES;
        #pragma unroll
        for (int i = 0; i < 4; i++) CP_ASYNC_16(st + sOff[i], gA[i] + s * BK);
        #pragma unroll
        for (int i = 0; i < 4; i++)
            CP_ASYNC_16(st + A_TILE_BYTES + sOff[i], gB[i] + s * BK);
        CP_COMMIT();
    }

    const int lm_row  = lid & 15;
    const int lm_half = lid >> 4;
    const int lb_j    = lid >> 3;
    const int lb_nin  = ((lb_j >> 1) << 3) + (lid & 7);
    const int lb_koff = (lb_j & 1) * 16;

    int st_idx = 0;
    for (int kt = 0; kt < NK; kt++) {
        CP_WAIT(1);
        __syncthreads();

        if (kt + STAGES - 1 < NK) {
            const int kn = kt + STAGES - 1;
            int si = st_idx + 2; if (si >= STAGES) si -= STAGES;
            uint32_t st = sb + si * STAGE_BYTES;
            #pragma unroll
            for (int i = 0; i < 4; i++) CP_ASYNC_16(st + sOff[i], gA[i] + kn * BK);
            #pragma unroll
            for (int i = 0; i < 4; i++)
                CP_ASYNC_16(st + A_TILE_BYTES + sOff[i], gB[i] + kn * BK);
        }
        CP_COMMIT();

        const uint32_t stA = sb + st_idx * STAGE_BYTES + (warp_m * 64) * ROW_BYTES;
        const uint32_t stB = sb + st_idx * STAGE_BYTES + A_TILE_BYTES
                           + (warp_n * 32) * ROW_BYTES;

        #pragma unroll
        for (int kk = 0; kk < 4; kk++) {   // four k16 steps per BK=64
            uint32_t a[4][4];
            #pragma unroll
            for (int mi = 0; mi < 4; mi++) {
                uint32_t ad = stA + (mi * 16 + lm_row) * ROW_BYTES
                            + kk * 32 + lm_half * 16;
                LDSM_X4(a[mi][0], a[mi][1], a[mi][2], a[mi][3], ad);
            }
            uint32_t b[4][2];
            #pragma unroll
            for (int nj = 0; nj < 2; nj++) {   // two n16 groups = 32 cols
                uint32_t bd = stB + (nj * 16 + lb_nin) * ROW_BYTES
                            + kk * 32 + lb_koff;
                LDSM_X4(b[2*nj][0], b[2*nj][1], b[2*nj+1][0], b[2*nj+1][1], bd);
            }
            #pragma unroll
            for (int mi = 0; mi < 4; mi++)
                #pragma unroll
                for (int nf = 0; nf < 4; nf++)
                    MMA_16816_F16(ch[mi][nf][0], ch[mi][nf][1],
                                  a[mi][0], a[mi][1], a[mi][2], a[mi][3],
                                  b[nf][0], b[nf][1]);

            if (kk & 1) {
                // promote K=32 window into fp32 and reset fp16 accumulators
                #pragma unroll
                for (int mi = 0; mi < 4; mi++)
                    #pragma unroll
                    for (int nf = 0; nf < 4; nf++) {
                        float2 f0 = __half22float2(
                            *reinterpret_cast<__half2*>(&ch[mi][nf][0]));
                        float2 f1 = __half22float2(
                            *reinterpret_cast<__half2*>(&ch[mi][nf][1]));
                        c[mi][nf][0] += f0.x;
                        c[mi][nf][1] += f0.y;
                        c[mi][nf][2] += f1.x;
                        c[mi][nf][3] += f1.y;
                        ch[mi][nf][0] = 0u;
                        ch[mi][nf][1] = 0u;
                    }
            }
        }
        if (++st_idx == STAGES) st_idx = 0;
    }

    // ---- epilogue ----
    const int er = lid >> 2, ec = (lid & 3) * 2;
    #pragma unroll
    for (int mi = 0; mi < 4; mi++) {
        const int gm0 = bm * BM + warp_m * 64 + mi * 16 + er;
        #pragma unroll
        for (int nf = 0; nf < 4; nf++) {
            const int gn = bn * BN + warp_n * 32 + nf * 8 + ec;
            const float b0 = __ldg(bias + gn), b1 = __ldg(bias + gn + 1);
            float2 v0 = {c[mi][nf][0] + b0, c[mi][nf][1] + b1};
            float2 v1 = {c[mi][nf][2] + b0, c[mi][nf][3] + b1};
            *reinterpret_cast<float2*>(out + (size_t)gm0 * OUT_F + gn) = v0;
            *reinterpret_cast<float2*>(out + (size_t)(gm0 + 8) * OUT_F + gn) = v1;
        }
    }
}

// ============================================================================
// Host launch
// ============================================================================
extern "C" void kernel_launch(void* const* d_in, const int* in_sizes, int n_in,
                              void* d_out, int out_size) {
    (void)in_sizes; (void)n_in; (void)out_size;
    const float* x     = (const float*)d_in[0];
    const int*   Wq    = (const int*)d_in[1];
    const float* scale = (const float*)d_in[2];
    const float* zero  = (const float*)d_in[3];
    const float* bias  = (const float*)d_in[4];
    float* out = (float*)d_out;

    void *pX = nullptr, *pW = nullptr;
    cudaGetSymbolAddress(&pX, g_X16);
    cudaGetSymbolAddress(&pW, g_W16);

    prep_kernel<<<PREP_BLOCKS, 256>>>((const float4*)x, (uint2*)pX,
                                      Wq, scale, zero, (__half*)pW);

    cudaFuncSetAttribute(gemm_f16_kernel, cudaFuncAttributeMaxDynamicSharedMemorySize,
                         SMEM_TOTAL);
    dim3 grid(OUT_F / BN, TOKENS / BM);   // (32, 64) = 2048 CTAs
    gemm_f16_kernel<<<grid, 256, SMEM_TOTAL>>>((const __half*)pX, (const __half*)pW,
                                               bias, out);
}

// round 11
// speedup vs baseline: 1.3868x; 1.3868x over previous
#include <cuda_runtime.h>
#include <cuda_fp16.h>
#include <cstdint>

// Problem dims
#define TOKENS 8192
#define IN_F   4096
#define OUT_F  4096
#define GROUPS (OUT_F * IN_F / 64)   // 262144
#define HALF_G (GROUPS / 2)          // 131072
#define PACKED (HALF_G * 64)         // 8388608

// Scratch: fp16 copies of x and dequantized W (device globals — no allocs)
__device__ __align__(1024) __half g_X16[(size_t)TOKENS * IN_F];  // 64 MB
__device__ __align__(1024) __half g_W16[(size_t)OUT_F * IN_F];   // 32 MB

// ============================================================================
// Merged prep kernel: half the blocks convert x fp32->fp16, half dequant W.
// ============================================================================
#define PREP_BLOCKS 8192
#define PREP_SPLIT  4096

__global__ void prep_kernel(const float4* __restrict__ x, uint2* __restrict__ oX,
                            const int* __restrict__ Wq, const float* __restrict__ scale,
                            const float* __restrict__ zero, __half* __restrict__ w16) {
    if (blockIdx.x < PREP_SPLIT) {
        const int n4 = TOKENS * IN_F / 4;
        for (int i = blockIdx.x * blockDim.x + threadIdx.x; i < n4;
             i += PREP_SPLIT * blockDim.x) {
            float4 v = x[i];
            union { __half2 h; unsigned u; } c0, c1;
            c0.h = __floats2half2_rn(v.x, v.y);
            c1.h = __floats2half2_rn(v.z, v.w);
            uint2 u; u.x = c0.u; u.y = c1.u;
            oX[i] = u;
        }
    } else {
        for (int i = (blockIdx.x - PREP_SPLIT) * blockDim.x + threadIdx.x; i < PACKED;
             i += (PREP_BLOCKS - PREP_SPLIT) * blockDim.x) {
            int q = Wq[i];
            int g = i >> 6;
            float s1 = __ldg(scale + g),          z1 = __ldg(zero + g);
            float s2 = __ldg(scale + g + HALF_G), z2 = __ldg(zero + g + HALF_G);
            w16[i]          = __float2half_rn(((float)((q >> 4) & 0xF) - z1) * s1);
            w16[i + PACKED] = __float2half_rn(((float)(q & 0xF)        - z2) * s2);
        }
    }
}

// ============================================================================
// GEMM: out[8192,4096] = X16 @ W16^T + bias
// fp16 inputs, fp16 mma accumulation over K=128 windows (2 kt iterations),
// promoted to fp32 between windows. f16-accum HMMA measured at rt~8 cyc/SMSP
// (2x the f32-accum rate); wide windows amortize the promotion WAR bubble.
// CTA tile 128(M) x 128(N) x 64(K), 3 cp.async stages, 256 threads,
// warp grid 2(m) x 4(n) -> 64x32 per warp (4 m16 x 4 n8 frags).
// SMEM rows padded to 72 halves (144B): conflict-free ldmatrix phases.
// ============================================================================
#define BM 128
#define BN 128
#define BK 64
#define STAGES 3
#define ROW_HALFS 72
#define ROW_BYTES (ROW_HALFS * 2)              // 144
#define A_TILE_BYTES (BM * ROW_BYTES)          // 18432
#define B_TILE_BYTES (BN * ROW_BYTES)          // 18432
#define STAGE_BYTES (A_TILE_BYTES + B_TILE_BYTES)   // 36864
#define SMEM_TOTAL (STAGES * STAGE_BYTES)      // 110592

__device__ __forceinline__ uint32_t smem_u32(const void* p) {
    uint32_t a;
    asm("{ .reg .u64 t; cvta.to.shared.u64 t, %1; cvt.u32.u64 %0, t; }"
        : "=r"(a) : "l"(p));
    return a;
}

#define CP_ASYNC_16(dst_u32, src_ptr) \
    asm volatile("cp.async.cg.shared.global [%0], [%1], 16;" \
        :: "r"(dst_u32), "l"(src_ptr) : "memory")
#define CP_COMMIT() asm volatile("cp.async.commit_group;" ::: "memory")
#define CP_WAIT(n)  asm volatile("cp.async.wait_group %0;" :: "n"(n) : "memory")

#define LDSM_X4(r0, r1, r2, r3, addr) \
    asm volatile("ldmatrix.sync.aligned.m8n8.x4.shared.b16 {%0,%1,%2,%3}, [%4];" \
        : "=r"(r0), "=r"(r1), "=r"(r2), "=r"(r3) : "r"(addr))

// fp16-accumulate mma: D/C are 2 x .f16x2 regs
#define MMA_16816_F16(d0, d1, a0, a1, a2, a3, b0, b1) \
    asm volatile("mma.sync.aligned.m16n8k16.row.col.f16.f16.f16.f16 " \
        "{%0,%1}, {%2,%3,%4,%5}, {%6,%7}, {%0,%1};" \
        : "+r"(d0), "+r"(d1) \
        : "r"(a0), "r"(a1), "r"(a2), "r"(a3), "r"(b0), "r"(b1))

__global__ void __launch_bounds__(256, 2)
gemm_f16_kernel(const __half* __restrict__ X16, const __half* __restrict__ W16,
                const float* __restrict__ bias, float* __restrict__ out) {
    extern __shared__ __align__(128) char smem[];
    const uint32_t sb = smem_u32(smem);
    const int tid = threadIdx.x;
    const int wid = tid >> 5, lid = tid & 31;
    const int warp_m = wid & 1;        // 0..1 -> 64 rows
    const int warp_n = wid >> 1;       // 0..3 -> 32 cols
    const int bn = blockIdx.x, bm = blockIdx.y;

    // ---- cp.async slots: each tile [128][64] = 1024 16B vectors, 4/thread ----
    const __half* gAbase = X16 + (size_t)(bm * BM) * IN_F;
    const __half* gBbase = W16 + (size_t)(bn * BN) * IN_F;
    uint32_t sOff[4];
    const __half* gA[4];
    const __half* gB[4];
    #pragma unroll
    for (int i = 0; i < 4; i++) {
        int v = tid + 256 * i;
        int r = v >> 3, c8 = v & 7;
        sOff[i] = r * ROW_BYTES + c8 * 16;
        gA[i] = gAbase + (size_t)r * IN_F + c8 * 8;
        gB[i] = gBbase + (size_t)r * IN_F + c8 * 8;
    }

    float c[4][4][4];
    #pragma unroll
    for (int mi = 0; mi < 4; mi++)
        #pragma unroll
        for (int nf = 0; nf < 4; nf++)
            c[mi][nf][0] = c[mi][nf][1] = c[mi][nf][2] = c[mi][nf][3] = 0.f;

    uint32_t ch[4][4][2];   // fp16 window accumulators (half2 pairs)
    #pragma unroll
    for (int mi = 0; mi < 4; mi++)
        #pragma unroll
        for (int nf = 0; nf < 4; nf++)
            ch[mi][nf][0] = ch[mi][nf][1] = 0u;

    const int NK = IN_F / BK;  // 64

    // ---- prologue ----
    #pragma unroll
    for (int s = 0; s < STAGES - 1; s++) {
        uint32_t st = sb + s * STAGE_BYTES;
        #pragma unroll
        for (int i = 0; i < 4; i++) CP_ASYNC_16(st + sOff[i], gA[i] + s * BK);
        #pragma unroll
        for (int i = 0; i < 4; i++)
            CP_ASYNC_16(st + A_TILE_BYTES + sOff[i], gB[i] + s * BK);
        CP_COMMIT();
    }

    const int lm_row  = lid & 15;
    const int lm_half = lid >> 4;
    const int lb_j    = lid >> 3;
    const int lb_nin  = ((lb_j >> 1) << 3) + (lid & 7);
    const int lb_koff = (lb_j & 1) * 16;

    int st_idx = 0;
    for (int kt = 0; kt < NK; kt++) {
        CP_WAIT(1);
        __syncthreads();

        if (kt + STAGES - 1 < NK) {
            const int kn = kt + STAGES - 1;
            int si = st_idx + 2; if (si >= STAGES) si -= STAGES;
            uint32_t st = sb + si * STAGE_BYTES;
            #pragma unroll
            for (int i = 0; i < 4; i++) CP_ASYNC_16(st + sOff[i], gA[i] + kn * BK);
            #pragma unroll
            for (int i = 0; i < 4; i++)
                CP_ASYNC_16(st + A_TILE_BYTES + sOff[i], gB[i] + kn * BK);
        }
        CP_COMMIT();

        const uint32_t stA = sb + st_idx * STAGE_BYTES + (warp_m * 64) * ROW_BYTES;
        const uint32_t stB = sb + st_idx * STAGE_BYTES + A_TILE_BYTES
                           + (warp_n * 32) * ROW_BYTES;

        #pragma unroll
        for (int kk = 0; kk < 4; kk++) {   // four k16 steps per BK=64
            uint32_t a[4][4];
            #pragma unroll
            for (int mi = 0; mi < 4; mi++) {
                uint32_t ad = stA + (mi * 16 + lm_row) * ROW_BYTES
                            + kk * 32 + lm_half * 16;
                LDSM_X4(a[mi][0], a[mi][1], a[mi][2], a[mi][3], ad);
            }
            uint32_t b[4][2];
            #pragma unroll
            for (int nj = 0; nj < 2; nj++) {   // two n16 groups = 32 cols
                uint32_t bd = stB + (nj * 16 + lb_nin) * ROW_BYTES
                            + kk * 32 + lb_koff;
                LDSM_X4(b[2*nj][0], b[2*nj][1], b[2*nj+1][0], b[2*nj+1][1], bd);
            }
            #pragma unroll
            for (int mi = 0; mi < 4; mi++)
                #pragma unroll
                for (int nf = 0; nf < 4; nf++)
                    MMA_16816_F16(ch[mi][nf][0], ch[mi][nf][1],
                                  a[mi][0], a[mi][1], a[mi][2], a[mi][3],
                                  b[nf][0], b[nf][1]);
        }

        // promote K=128 window (every second kt) into fp32, reset fp16 accums
        if (kt & 1) {
            #pragma unroll
            for (int mi = 0; mi < 4; mi++)
                #pragma unroll
                for (int nf = 0; nf < 4; nf++) {
                    float2 f0 = __half22float2(
                        *reinterpret_cast<__half2*>(&ch[mi][nf][0]));
                    float2 f1 = __half22float2(
                        *reinterpret_cast<__half2*>(&ch[mi][nf][1]));
                    c[mi][nf][0] += f0.x;
                    c[mi][nf][1] += f0.y;
                    c[mi][nf][2] += f1.x;
                    c[mi][nf][3] += f1.y;
                    ch[mi][nf][0] = 0u;
                    ch[mi][nf][1] = 0u;
                }
        }
        if (++st_idx == STAGES) st_idx = 0;
    }

    // ---- epilogue ----
    const int er = lid >> 2, ec = (lid & 3) * 2;
    #pragma unroll
    for (int mi = 0; mi < 4; mi++) {
        const int gm0 = bm * BM + warp_m * 64 + mi * 16 + er;
        #pragma unroll
        for (int nf = 0; nf < 4; nf++) {
            const int gn = bn * BN + warp_n * 32 + nf * 8 + ec;
            const float b0 = __ldg(bias + gn), b1 = __ldg(bias + gn + 1);
            float2 v0 = {c[mi][nf][0] + b0, c[mi][nf][1] + b1};
            float2 v1 = {c[mi][nf][2] + b0, c[mi][nf][3] + b1};
            *reinterpret_cast<float2*>(out + (size_t)gm0 * OUT_F + gn) = v0;
            *reinterpret_cast<float2*>(out + (size_t)(gm0 + 8) * OUT_F + gn) = v1;
        }
    }
}

// ============================================================================
// Host launch
// ============================================================================
extern "C" void kernel_launch(void* const* d_in, const int* in_sizes, int n_in,
                              void* d_out, int out_size) {
    (void)in_sizes; (void)n_in; (void)out_size;
    const float* x     = (const float*)d_in[0];
    const int*   Wq    = (const int*)d_in[1];
    const float* scale = (const float*)d_in[2];
    const float* zero  = (const float*)d_in[3];
    const float* bias  = (const float*)d_in[4];
    float* out = (float*)d_out;

    void *pX = nullptr, *pW = nullptr;
    cudaGetSymbolAddress(&pX, g_X16);
    cudaGetSymbolAddress(&pW, g_W16);

    prep_kernel<<<PREP_BLOCKS, 256>>>((const float4*)x, (uint2*)pX,
                                      Wq, scale, zero, (__half*)pW);

    cudaFuncSetAttribute(gemm_f16_kernel, cudaFuncAttributeMaxDynamicSharedMemorySize,
                         SMEM_TOTAL);
    dim3 grid(OUT_F / BN, TOKENS / BM);   // (32, 64) = 2048 CTAs
    gemm_f16_kernel<<<grid, 256, SMEM_TOTAL>>>((const __half*)pX, (const __half*)pW,
                                               bias, out);
}

// round 12
// speedup vs baseline: 1.3891x; 1.0017x over previous
#include <cuda_runtime.h>
#include <cuda_fp16.h>
#include <cstdint>

// Problem dims
#define TOKENS 8192
#define IN_F   4096
#define OUT_F  4096
#define GROUPS (OUT_F * IN_F / 64)   // 262144
#define HALF_G (GROUPS / 2)          // 131072
#define PACKED (HALF_G * 64)         // 8388608

// Scratch: fp16 copies of x and dequantized W (device globals — no allocs)
__device__ __align__(1024) __half g_X16[(size_t)TOKENS * IN_F];  // 64 MB
__device__ __align__(1024) __half g_W16[(size_t)OUT_F * IN_F];   // 32 MB

// ============================================================================
// Merged prep kernel: half the blocks convert x fp32->fp16, half dequant W.
// ============================================================================
#define PREP_BLOCKS 8192
#define PREP_SPLIT  4096

__global__ void prep_kernel(const float4* __restrict__ x, uint2* __restrict__ oX,
                            const int* __restrict__ Wq, const float* __restrict__ scale,
                            const float* __restrict__ zero, __half* __restrict__ w16) {
    if (blockIdx.x < PREP_SPLIT) {
        const int n4 = TOKENS * IN_F / 4;
        for (int i = blockIdx.x * blockDim.x + threadIdx.x; i < n4;
             i += PREP_SPLIT * blockDim.x) {
            float4 v = x[i];
            union { __half2 h; unsigned u; } c0, c1;
            c0.h = __floats2half2_rn(v.x, v.y);
            c1.h = __floats2half2_rn(v.z, v.w);
            uint2 u; u.x = c0.u; u.y = c1.u;
            oX[i] = u;
        }
    } else {
        for (int i = (blockIdx.x - PREP_SPLIT) * blockDim.x + threadIdx.x; i < PACKED;
             i += (PREP_BLOCKS - PREP_SPLIT) * blockDim.x) {
            int q = Wq[i];
            int g = i >> 6;
            float s1 = __ldg(scale + g),          z1 = __ldg(zero + g);
            float s2 = __ldg(scale + g + HALF_G), z2 = __ldg(zero + g + HALF_G);
            w16[i]          = __float2half_rn(((float)((q >> 4) & 0xF) - z1) * s1);
            w16[i + PACKED] = __float2half_rn(((float)(q & 0xF)        - z2) * s2);
        }
    }
}

// ============================================================================
// GEMM: out[8192,4096] = X16 @ W16^T + bias
// fp16 inputs, fp16 mma accumulation over K=128 windows, promoted to fp32.
// TLP-focused config: CTA tile 128(M) x 64(N) x 64(K), warp tile 32x32,
// 2 cp.async stages, 256 threads, ~80 regs -> 3 CTAs/SM (24 warps: one CTA's
// barrier/LDSM/promotion bubbles are filled by the other two CTAs' MMAs).
// SMEM rows padded to 72 halves (144B): conflict-free ldmatrix phases.
// ============================================================================
#define BM 128
#define BN 64
#define BK 64
#define STAGES 2
#define ROW_HALFS 72
#define ROW_BYTES (ROW_HALFS * 2)              // 144
#define A_TILE_BYTES (BM * ROW_BYTES)          // 18432
#define B_TILE_BYTES (BN * ROW_BYTES)          // 9216
#define STAGE_BYTES (A_TILE_BYTES + B_TILE_BYTES)   // 27648
#define SMEM_TOTAL (STAGES * STAGE_BYTES)      // 55296 per CTA

__device__ __forceinline__ uint32_t smem_u32(const void* p) {
    uint32_t a;
    asm("{ .reg .u64 t; cvta.to.shared.u64 t, %1; cvt.u32.u64 %0, t; }"
        : "=r"(a) : "l"(p));
    return a;
}

#define CP_ASYNC_16(dst_u32, src_ptr) \
    asm volatile("cp.async.cg.shared.global [%0], [%1], 16;" \
        :: "r"(dst_u32), "l"(src_ptr) : "memory")
#define CP_COMMIT() asm volatile("cp.async.commit_group;" ::: "memory")
#define CP_WAIT0()  asm volatile("cp.async.wait_group 0;" ::: "memory")

#define LDSM_X4(r0, r1, r2, r3, addr) \
    asm volatile("ldmatrix.sync.aligned.m8n8.x4.shared.b16 {%0,%1,%2,%3}, [%4];" \
        : "=r"(r0), "=r"(r1), "=r"(r2), "=r"(r3) : "r"(addr))

// fp16-accumulate mma: D/C are 2 x .f16x2 regs
#define MMA_16816_F16(d0, d1, a0, a1, a2, a3, b0, b1) \
    asm volatile("mma.sync.aligned.m16n8k16.row.col.f16.f16.f16.f16 " \
        "{%0,%1}, {%2,%3,%4,%5}, {%6,%7}, {%0,%1};" \
        : "+r"(d0), "+r"(d1) \
        : "r"(a0), "r"(a1), "r"(a2), "r"(a3), "r"(b0), "r"(b1))

__global__ void __launch_bounds__(256, 3)
gemm_f16_kernel(const __half* __restrict__ X16, const __half* __restrict__ W16,
                const float* __restrict__ bias, float* __restrict__ out) {
    extern __shared__ __align__(128) char smem[];
    const uint32_t sb = smem_u32(smem);
    const int tid = threadIdx.x;
    const int wid = tid >> 5, lid = tid & 31;
    const int warp_m = wid & 3;        // 0..3 -> 32 rows each
    const int warp_n = wid >> 2;       // 0..1 -> 32 cols each
    const int bn = blockIdx.x, bm = blockIdx.y;

    // ---- cp.async slots ----
    // A tile [128][64]: 1024 16B vectors -> 4/thread; B tile [64][64]: 512 -> 2/thread
    const __half* gAbase = X16 + (size_t)(bm * BM) * IN_F;
    const __half* gBbase = W16 + (size_t)(bn * BN) * IN_F;
    uint32_t sAoff[4], sBoff[2];
    const __half* gA[4];
    const __half* gB[2];
    #pragma unroll
    for (int i = 0; i < 4; i++) {
        int v = tid + 256 * i;
        int r = v >> 3, c8 = v & 7;
        sAoff[i] = r * ROW_BYTES + c8 * 16;
        gA[i] = gAbase + (size_t)r * IN_F + c8 * 8;
    }
    #pragma unroll
    for (int i = 0; i < 2; i++) {
        int v = tid + 256 * i;
        int r = v >> 3, c8 = v & 7;
        sBoff[i] = r * ROW_BYTES + c8 * 16;
        gB[i] = gBbase + (size_t)r * IN_F + c8 * 8;
    }

    float c[2][4][4];
    #pragma unroll
    for (int mi = 0; mi < 2; mi++)
        #pragma unroll
        for (int nf = 0; nf < 4; nf++)
            c[mi][nf][0] = c[mi][nf][1] = c[mi][nf][2] = c[mi][nf][3] = 0.f;

    uint32_t ch[2][4][2];   // fp16 window accumulators
    #pragma unroll
    for (int mi = 0; mi < 2; mi++)
        #pragma unroll
        for (int nf = 0; nf < 4; nf++)
            ch[mi][nf][0] = ch[mi][nf][1] = 0u;

    const int NK = IN_F / BK;  // 64

    // ---- prologue: fill stage 0 ----
    {
        uint32_t st = sb;
        #pragma unroll
        for (int i = 0; i < 4; i++) CP_ASYNC_16(st + sAoff[i], gA[i]);
        #pragma unroll
        for (int i = 0; i < 2; i++)
            CP_ASYNC_16(st + A_TILE_BYTES + sBoff[i], gB[i]);
        CP_COMMIT();
    }

    const int lm_row  = lid & 15;
    const int lm_half = lid >> 4;
    const int lb_j    = lid >> 3;
    const int lb_nin  = ((lb_j >> 1) << 3) + (lid & 7);
    const int lb_koff = (lb_j & 1) * 16;

    for (int kt = 0; kt < NK; kt++) {
        // stage kt&1 is the only pending group -> wait for it
        CP_WAIT0();
        __syncthreads();   // also guarantees all warps finished reading stage (kt+1)&1

        // prefetch next chunk into the other stage (safe: post-sync)
        if (kt + 1 < NK) {
            uint32_t st = sb + ((kt + 1) & 1) * STAGE_BYTES;
            #pragma unroll
            for (int i = 0; i < 4; i++)
                CP_ASYNC_16(st + sAoff[i], gA[i] + (kt + 1) * BK);
            #pragma unroll
            for (int i = 0; i < 2; i++)
                CP_ASYNC_16(st + A_TILE_BYTES + sBoff[i], gB[i] + (kt + 1) * BK);
            CP_COMMIT();
        }

        const uint32_t stA = sb + (kt & 1) * STAGE_BYTES + (warp_m * 32) * ROW_BYTES;
        const uint32_t stB = sb + (kt & 1) * STAGE_BYTES + A_TILE_BYTES
                           + (warp_n * 32) * ROW_BYTES;

        #pragma unroll
        for (int kk = 0; kk < 4; kk++) {   // four k16 steps per BK=64
            uint32_t a[2][4];
            #pragma unroll
            for (int mi = 0; mi < 2; mi++) {
                uint32_t ad = stA + (mi * 16 + lm_row) * ROW_BYTES
                            + kk * 32 + lm_half * 16;
                LDSM_X4(a[mi][0], a[mi][1], a[mi][2], a[mi][3], ad);
            }
            uint32_t b[4][2];
            #pragma unroll
            for (int nj = 0; nj < 2; nj++) {   // two n16 groups = 32 cols
                uint32_t bd = stB + (nj * 16 + lb_nin) * ROW_BYTES
                            + kk * 32 + lb_koff;
                LDSM_X4(b[2*nj][0], b[2*nj][1], b[2*nj+1][0], b[2*nj+1][1], bd);
            }
            #pragma unroll
            for (int mi = 0; mi < 2; mi++)
                #pragma unroll
                for (int nf = 0; nf < 4; nf++)
                    MMA_16816_F16(ch[mi][nf][0], ch[mi][nf][1],
                                  a[mi][0], a[mi][1], a[mi][2], a[mi][3],
                                  b[nf][0], b[nf][1]);
        }

        // promote K=128 window (every second kt) into fp32, reset fp16 accums
        if (kt & 1) {
            #pragma unroll
            for (int mi = 0; mi < 2; mi++)
                #pragma unroll
                for (int nf = 0; nf < 4; nf++) {
                    float2 f0 = __half22float2(
                        *reinterpret_cast<__half2*>(&ch[mi][nf][0]));
                    float2 f1 = __half22float2(
                        *reinterpret_cast<__half2*>(&ch[mi][nf][1]));
                    c[mi][nf][0] += f0.x;
                    c[mi][nf][1] += f0.y;
                    c[mi][nf][2] += f1.x;
                    c[mi][nf][3] += f1.y;
                    ch[mi][nf][0] = 0u;
                    ch[mi][nf][1] = 0u;
                }
        }
    }

    // ---- epilogue ----
    const int er = lid >> 2, ec = (lid & 3) * 2;
    #pragma unroll
    for (int mi = 0; mi < 2; mi++) {
        const int gm0 = bm * BM + warp_m * 32 + mi * 16 + er;
        #pragma unroll
        for (int nf = 0; nf < 4; nf++) {
            const int gn = bn * BN + warp_n * 32 + nf * 8 + ec;
            const float b0 = __ldg(bias + gn), b1 = __ldg(bias + gn + 1);
            float2 v0 = {c[mi][nf][0] + b0, c[mi][nf][1] + b1};
            float2 v1 = {c[mi][nf][2] + b0, c[mi][nf][3] + b1};
            *reinterpret_cast<float2*>(out + (size_t)gm0 * OUT_F + gn) = v0;
            *reinterpret_cast<float2*>(out + (size_t)(gm0 + 8) * OUT_F + gn) = v1;
        }
    }
}

// ============================================================================
// Host launch
// ============================================================================
extern "C" void kernel_launch(void* const* d_in, const int* in_sizes, int n_in,
                              void* d_out, int out_size) {
    (void)in_sizes; (void)n_in; (void)out_size;
    const float* x     = (const float*)d_in[0];
    const int*   Wq    = (const int*)d_in[1];
    const float* scale = (const float*)d_in[2];
    const float* zero  = (const float*)d_in[3];
    const float* bias  = (const float*)d_in[4];
    float* out = (float*)d_out;

    void *pX = nullptr, *pW = nullptr;
    cudaGetSymbolAddress(&pX, g_X16);
    cudaGetSymbolAddress(&pW, g_W16);

    prep_kernel<<<PREP_BLOCKS, 256>>>((const float4*)x, (uint2*)pX,
                                      Wq, scale, zero, (__half*)pW);

    cudaFuncSetAttribute(gemm_f16_kernel, cudaFuncAttributeMaxDynamicSharedMemorySize,
                         SMEM_TOTAL);
    dim3 grid(OUT_F / BN, TOKENS / BM);   // (64, 64) = 4096 CTAs
    gemm_f16_kernel<<<grid, 256, SMEM_TOTAL>>>((const __half*)pX, (const __half*)pW,
                                               bias, out);
}